// round 12
// baseline (speedup 1.0000x reference)
#include <cuda_runtime.h>
#include <cuda_bf16.h>
#include <cstdint>

#define DCH 128
#define NMAX 100000
#define EMAX 1600064
#define SW(o) ((o) ^ (((o) >> 3) & 0x30))

// ---------------- scratch (device globals; no runtime allocation) ----------------
__device__ float  g_buf0[NMAX * DCH];     // agg (pre-BN activations)
__device__ float  g_buf1[NMAX * DCH];     // gemm output t / lin1 output
__device__ __nv_bfloat16 g_wh[3 * DCH * DCH];   // conv W transposed [l][n][k] hi
__device__ __nv_bfloat16 g_wl[3 * DCH * DCH];
__device__ __nv_bfloat16 g_l1h[2 * DCH * DCH];  // lin1 W transposed [n][k=256] hi
__device__ __nv_bfloat16 g_l1l[2 * DCH * DCH];
__device__ int    g_degi[NMAX];
__device__ float  g_dinv[NMAX];
__device__ int    g_csr_off[NMAX + 1];
__device__ int    g_cursor[NMAX];
__device__ int    g_csr_src[EMAX];
__device__ int    g_bsum[256];
__device__ double g_sum[DCH];
__device__ double g_sumsq[DCH];
__device__ float  g_scale[DCH];
__device__ float  g_shift[DCH];

// ---------------- helpers ----------------
__device__ __forceinline__ uint32_t sptr(const void* p) {
    return (uint32_t)__cvta_generic_to_shared(p);
}
__device__ __forceinline__ void ldsm4(unsigned r[4], uint32_t a) {
    asm volatile("ldmatrix.sync.aligned.m8n8.x4.shared.b16 {%0,%1,%2,%3}, [%4];\n"
                 : "=r"(r[0]), "=r"(r[1]), "=r"(r[2]), "=r"(r[3]) : "r"(a));
}
__device__ __forceinline__ void mma16816(float c[4], const unsigned a[4], const unsigned b[2]) {
    asm volatile(
        "mma.sync.aligned.m16n8k16.row.col.f32.bf16.bf16.f32 "
        "{%0,%1,%2,%3}, {%4,%5,%6,%7}, {%8,%9}, {%0,%1,%2,%3};\n"
        : "+f"(c[0]), "+f"(c[1]), "+f"(c[2]), "+f"(c[3])
        : "r"(a[0]), "r"(a[1]), "r"(a[2]), "r"(a[3]), "r"(b[0]), "r"(b[1]));
}
__device__ __forceinline__ void split_bf16(float v, __nv_bfloat16& h, __nv_bfloat16& l) {
    h = __float2bfloat16(v);
    l = __float2bfloat16(v - __bfloat162float(h));
}
__device__ __forceinline__ void cp_async16(uint32_t saddr, const void* gaddr) {
    asm volatile("cp.async.ca.shared.global [%0], [%1], 16;" :: "r"(saddr), "l"(gaddr));
}

// ---------------- degree / dinv ----------------
__global__ void k_deg_init(int* degi, int n) {
    int i = blockIdx.x * blockDim.x + threadIdx.x;
    if (i < n) degi[i] = 1;
}
__global__ void k_deg_count(const int* __restrict__ ei, int* degi, int E) {
    int e = blockIdx.x * blockDim.x + threadIdx.x;
    if (e < E) atomicAdd(&degi[ei[E + e]], 1);
}
__global__ void k_dinv(const int* __restrict__ degi, float* dinv, int n) {
    int i = blockIdx.x * blockDim.x + threadIdx.x;
    if (i < n) dinv[i] = rsqrtf((float)degi[i]);
}

// ---------------- CSR build ----------------
__global__ void k_scan1(const int* __restrict__ degi, int n) {
    __shared__ int sh[512];
    int i = blockIdx.x * 512 + threadIdx.x;
    int v = (i < n) ? (degi[i] - 1) : 0;
    sh[threadIdx.x] = v;
    __syncthreads();
    int val = v;
#pragma unroll
    for (int off = 1; off < 512; off <<= 1) {
        int t = (threadIdx.x >= off) ? sh[threadIdx.x - off] : 0;
        __syncthreads();
        val += t;
        sh[threadIdx.x] = val;
        __syncthreads();
    }
    if (i < n) g_csr_off[i] = val - v;
    if (threadIdx.x == 511) g_bsum[blockIdx.x] = val;
}
__global__ void k_scan2(int nb, int n) {
    __shared__ int sh[256];
    int v = (threadIdx.x < nb) ? g_bsum[threadIdx.x] : 0;
    sh[threadIdx.x] = v;
    __syncthreads();
    int val = v;
#pragma unroll
    for (int off = 1; off < 256; off <<= 1) {
        int t = (threadIdx.x >= off) ? sh[threadIdx.x - off] : 0;
        __syncthreads();
        val += t;
        sh[threadIdx.x] = val;
        __syncthreads();
    }
    if (threadIdx.x < nb) g_bsum[threadIdx.x] = val - v;
    if (threadIdx.x == 255) g_csr_off[n] = val;
}
__global__ void k_scan3(int n) {
    int i = blockIdx.x * 512 + threadIdx.x;
    if (i < n) {
        int o = g_csr_off[i] + g_bsum[blockIdx.x];
        g_csr_off[i] = o;
        g_cursor[i]  = o;
    }
}
__global__ void k_fill(const int* __restrict__ ei, int E) {
    int e = blockIdx.x * blockDim.x + threadIdx.x;
    if (e < E) {
        int d = ei[E + e];
        int slot = atomicAdd(&g_cursor[d], 1);
        g_csr_src[slot] = ei[e];
    }
}

// ---------------- weight prep: transpose to [n][k] and split ----------------
__global__ void k_wprep(const float* __restrict__ cw, const float* __restrict__ l1w) {
    int i = blockIdx.x * 256 + threadIdx.x;
    const int CONV = 3 * DCH * DCH;
    if (i < CONV) {
        int l = i / (DCH * DCH);
        int r = i % (DCH * DCH);
        int nn = r / DCH, k = r % DCH;
        float v = cw[(size_t)l * DCH * DCH + k * DCH + nn];
        split_bf16(v, g_wh[i], g_wl[i]);
    } else if (i < CONV + DCH * 2 * DCH) {
        int j = i - CONV;
        int nn = j / (2 * DCH), k = j % (2 * DCH);
        float v = l1w[(size_t)k * DCH + nn];
        split_bf16(v, g_l1h[j], g_l1l[j]);
    }
}

// ---------------- BN finalize: scale/shift from accumulated stats ----------------
__global__ void k_bn_finalize(const float* __restrict__ gamma,
                              const float* __restrict__ beta, int n) {
    int c = threadIdx.x;
    double mu = g_sum[c] / n;
    double var = g_sumsq[c] / n - mu * mu;
    float rs = (float)rsqrt(var + 1e-5);
    float g = gamma[c] * rs;
    g_scale[c] = g;
    g_shift[c] = beta[c] - (float)mu * g;
}

__global__ void k_bn_zero() {
    g_sum[threadIdx.x] = 0.0;
    g_sumsq[threadIdx.x] = 0.0;
}

// ---------------- tensor-core GEMM (mma.sync), SW64 smem, cp.async B pipeline ------
// C[n,128] = f(A)[n,K] @ Wt[128,K]^T (+bias)(+relu_out)
// f(A) = relu(A*g_scale + g_shift) if useBN, else A. A2 supplies k in [128,256).
// Split-bf16 3-term: C = Ah*Wh + Ah*Wl + Al*Wh.
// B double-buffered via cp.async: tile t+1 issued before A-convert of t, waited
// one phase later (latency covered by convert + mma).
__global__ __launch_bounds__(256, 2)
void k_mma_gemm(const float* __restrict__ A, const float* __restrict__ A2,
                const __nv_bfloat16* __restrict__ Bh, const __nv_bfloat16* __restrict__ Bl,
                const float* __restrict__ bias, int useBN,
                float* __restrict__ C, int n, int K, int relu)
{
    __shared__ __align__(128) __nv_bfloat16 sAh[4096];      // 128 rows x 64B (SW64)
    __shared__ __align__(128) __nv_bfloat16 sAl[4096];
    __shared__ __align__(128) __nv_bfloat16 sBh[2][4096];
    __shared__ __align__(128) __nv_bfloat16 sBl[2][4096];

    const int tid = threadIdx.x, lane = tid & 31, wid = tid >> 5;
    const int wm = wid & 3;
    const int wn = wid >> 2;
    const int row0 = blockIdx.x * 128;
    const uint32_t bAh = sptr(sAh), bAl = sptr(sAl);
    const uint32_t bBh[2] = { sptr(sBh[0]), sptr(sBh[1]) };
    const uint32_t bBl[2] = { sptr(sBl[0]), sptr(sBl[1]) };

    float c[2][8][4];
#pragma unroll
    for (int i = 0; i < 2; i++)
#pragma unroll
        for (int j = 0; j < 8; j++)
#pragma unroll
            for (int q = 0; q < 4; q++) c[i][j][q] = 0.f;

    const int T = K >> 5;   // k-tiles of 32

    // prologue: B tile 0 -> stage 0
#pragma unroll
    for (int p = 0; p < 2; p++) {
        int idx = tid + p * 256;
        int r = idx >> 2, seg = idx & 3;
        size_t go = (size_t)r * K + seg * 8;
        uint32_t so = SW((uint32_t)(r * 64 + seg * 16));
        cp_async16(bBh[0] + so, Bh + go);
        cp_async16(bBl[0] + so, Bl + go);
    }
    asm volatile("cp.async.commit_group;" ::: "memory");

    for (int t = 0; t < T; t++) {
        const int kk = t * 32;
        // issue B tile t+1 into the other stage
        if (t + 1 < T) {
            int nb = (t + 1) & 1;
            int nkk = kk + 32;
#pragma unroll
            for (int p = 0; p < 2; p++) {
                int idx = tid + p * 256;
                int r = idx >> 2, seg = idx & 3;
                size_t go = (size_t)r * K + nkk + seg * 8;
                uint32_t so = SW((uint32_t)(r * 64 + seg * 16));
                cp_async16(bBh[nb] + so, Bh + go);
                cp_async16(bBl[nb] + so, Bl + go);
            }
            asm volatile("cp.async.commit_group;" ::: "memory");
        }
        // A tile t: fp32 load -> (BN+ReLU) -> split bf16 hi/lo -> SW64 smem
        const float* ap;
        int kb;
        bool isA;
        if (A2 != nullptr && kk >= 128) { ap = A2; kb = kk - 128; isA = false; }
        else                            { ap = A;  kb = kk; isA = true; }
        const bool bn = useBN && isA;
#pragma unroll
        for (int p = 0; p < 2; p++) {
            int idx = tid + p * 256;
            int r = idx >> 2, seg = idx & 3;
            int grow = row0 + r;
            float v[8];
#pragma unroll
            for (int q = 0; q < 8; q++) v[q] = 0.f;
            if (grow < n) {
                const float* base = ap + (size_t)grow * DCH + kb + seg * 8;
                *(float4*)&v[0] = *(const float4*)base;
                *(float4*)&v[4] = *(const float4*)(base + 4);
            }
            if (bn) {
                int c0 = kb + seg * 8;
                float4 sc0 = __ldg((const float4*)(g_scale + c0));
                float4 sc1 = __ldg((const float4*)(g_scale + c0 + 4));
                float4 sh0 = __ldg((const float4*)(g_shift + c0));
                float4 sh1 = __ldg((const float4*)(g_shift + c0 + 4));
                v[0] = fmaxf(fmaf(v[0], sc0.x, sh0.x), 0.f);
                v[1] = fmaxf(fmaf(v[1], sc0.y, sh0.y), 0.f);
                v[2] = fmaxf(fmaf(v[2], sc0.z, sh0.z), 0.f);
                v[3] = fmaxf(fmaf(v[3], sc0.w, sh0.w), 0.f);
                v[4] = fmaxf(fmaf(v[4], sc1.x, sh1.x), 0.f);
                v[5] = fmaxf(fmaf(v[5], sc1.y, sh1.y), 0.f);
                v[6] = fmaxf(fmaf(v[6], sc1.z, sh1.z), 0.f);
                v[7] = fmaxf(fmaf(v[7], sc1.w, sh1.w), 0.f);
            }
            __nv_bfloat16 hb[8], lb[8];
#pragma unroll
            for (int q = 0; q < 8; q++) split_bf16(v[q], hb[q], lb[q]);
            uint32_t so = SW((uint32_t)(r * 64 + seg * 16));
            *(uint4*)((char*)sAh + so) = *(uint4*)hb;
            *(uint4*)((char*)sAl + so) = *(uint4*)lb;
        }
        // wait for B tile t (leave t+1 in flight)
        if (t + 1 < T)
            asm volatile("cp.async.wait_group 1;" ::: "memory");
        else
            asm volatile("cp.async.wait_group 0;" ::: "memory");
        __syncthreads();

        const uint32_t curBh = bBh[t & 1], curBl = bBl[t & 1];
#pragma unroll
        for (int kq = 0; kq < 2; kq++) {
            unsigned a_h[2][4], a_l[2][4], b_h[8][2], b_l[8][2];
            int arow = wm * 32 + (lane & 15);
            uint32_t abyte = (uint32_t)(kq * 32 + ((lane & 16) ? 16 : 0));
#pragma unroll
            for (int i = 0; i < 2; i++) {
                uint32_t off = SW((uint32_t)((arow + i * 16) * 64) + abyte);
                ldsm4(a_h[i], bAh + off);
                ldsm4(a_l[i], bAl + off);
            }
            uint32_t bbyte = (uint32_t)(kq * 32 + ((lane & 8) ? 16 : 0));
#pragma unroll
            for (int jp = 0; jp < 4; jp++) {
                int brow = wn * 64 + jp * 16 + ((lane & 16) ? 8 : 0) + (lane & 7);
                uint32_t off = SW((uint32_t)(brow * 64) + bbyte);
                unsigned tr[4];
                ldsm4(tr, curBh + off);
                b_h[jp * 2][0] = tr[0]; b_h[jp * 2][1] = tr[1];
                b_h[jp * 2 + 1][0] = tr[2]; b_h[jp * 2 + 1][1] = tr[3];
                ldsm4(tr, curBl + off);
                b_l[jp * 2][0] = tr[0]; b_l[jp * 2][1] = tr[1];
                b_l[jp * 2 + 1][0] = tr[2]; b_l[jp * 2 + 1][1] = tr[3];
            }
#pragma unroll
            for (int i = 0; i < 2; i++)
#pragma unroll
                for (int j = 0; j < 8; j++) {
                    mma16816(c[i][j], a_h[i], b_h[j]);
                    mma16816(c[i][j], a_h[i], b_l[j]);
                    mma16816(c[i][j], a_l[i], b_h[j]);
                }
        }
        __syncthreads();
    }

#pragma unroll
    for (int i = 0; i < 2; i++) {
#pragma unroll
        for (int j = 0; j < 8; j++) {
            int col = wn * 64 + j * 8 + (lane & 3) * 2;
            float b0 = bias ? bias[col] : 0.f;
            float b1 = bias ? bias[col + 1] : 0.f;
            int r0 = row0 + wm * 32 + i * 16 + (lane >> 2);
            float v0 = c[i][j][0] + b0, v1 = c[i][j][1] + b1;
            float v2 = c[i][j][2] + b0, v3 = c[i][j][3] + b1;
            if (relu) {
                v0 = fmaxf(v0, 0.f); v1 = fmaxf(v1, 0.f);
                v2 = fmaxf(v2, 0.f); v3 = fmaxf(v3, 0.f);
            }
            if (r0 < n)     *(float2*)(C + (size_t)r0 * DCH + col)       = make_float2(v0, v1);
            if (r0 + 8 < n) *(float2*)(C + (size_t)(r0 + 8) * DCH + col) = make_float2(v2, v3);
        }
    }
}

// ---------------- GCN aggregation + fused BN statistics ----------------
__global__ __launch_bounds__(256)
void k_gather_stats(const float* __restrict__ t, const float* __restrict__ dinv,
                    const float* __restrict__ bias, float* __restrict__ agg, int n)
{
    __shared__ float sS[DCH], sQ[DCH];
    if (threadIdx.x < DCH) {
        sS[threadIdx.x] = 0.f;
        sQ[threadIdx.x] = 0.f;
    }
    __syncthreads();

    int gw = (blockIdx.x * blockDim.x + threadIdx.x) >> 5;
    int lane = threadIdx.x & 31;
    int nw = (gridDim.x * blockDim.x) >> 5;
    float4 bv = __ldg((const float4*)bias + lane);
    float4 ps = make_float4(0.f, 0.f, 0.f, 0.f);
    float4 pq = make_float4(0.f, 0.f, 0.f, 0.f);

    for (int node = gw; node < n; node += nw) {
        float di = __ldg(&dinv[node]);
        float4 tv = __ldg((const float4*)(t + (size_t)node * DCH) + lane);
        float w0 = di * di;
        float4 acc;
        acc.x = bv.x + w0 * tv.x;
        acc.y = bv.y + w0 * tv.y;
        acc.z = bv.z + w0 * tv.z;
        acc.w = bv.w + w0 * tv.w;
        int beg = __ldg(&g_csr_off[node]);
        int end = __ldg(&g_csr_off[node + 1]);
        int j = beg;
#pragma unroll 1
        for (; j + 4 <= end; j += 4) {
            int s0 = __ldg(&g_csr_src[j]);
            int s1 = __ldg(&g_csr_src[j + 1]);
            int s2 = __ldg(&g_csr_src[j + 2]);
            int s3 = __ldg(&g_csr_src[j + 3]);
            float wa = di * __ldg(&dinv[s0]);
            float wb = di * __ldg(&dinv[s1]);
            float wc = di * __ldg(&dinv[s2]);
            float wd = di * __ldg(&dinv[s3]);
            float4 va = __ldg((const float4*)(t + (size_t)s0 * DCH) + lane);
            float4 vb = __ldg((const float4*)(t + (size_t)s1 * DCH) + lane);
            float4 vc = __ldg((const float4*)(t + (size_t)s2 * DCH) + lane);
            float4 vd = __ldg((const float4*)(t + (size_t)s3 * DCH) + lane);
            acc.x += wa * va.x; acc.y += wa * va.y; acc.z += wa * va.z; acc.w += wa * va.w;
            acc.x += wb * vb.x; acc.y += wb * vb.y; acc.z += wb * vb.z; acc.w += wb * vb.w;
            acc.x += wc * vc.x; acc.y += wc * vc.y; acc.z += wc * vc.z; acc.w += wc * vc.w;
            acc.x += wd * vd.x; acc.y += wd * vd.y; acc.z += wd * vd.z; acc.w += wd * vd.w;
        }
        for (; j < end; j++) {
            int s = __ldg(&g_csr_src[j]);
            float w = di * __ldg(&dinv[s]);
            float4 v = __ldg((const float4*)(t + (size_t)s * DCH) + lane);
            acc.x += w * v.x;
            acc.y += w * v.y;
            acc.z += w * v.z;
            acc.w += w * v.w;
        }
        *((float4*)(agg + (size_t)node * DCH) + lane) = acc;
        ps.x += acc.x; ps.y += acc.y; ps.z += acc.z; ps.w += acc.w;
        pq.x += acc.x * acc.x; pq.y += acc.y * acc.y;
        pq.z += acc.z * acc.z; pq.w += acc.w * acc.w;
    }

    int c0 = lane * 4;
    atomicAdd(&sS[c0 + 0], ps.x);
    atomicAdd(&sS[c0 + 1], ps.y);
    atomicAdd(&sS[c0 + 2], ps.z);
    atomicAdd(&sS[c0 + 3], ps.w);
    atomicAdd(&sQ[c0 + 0], pq.x);
    atomicAdd(&sQ[c0 + 1], pq.y);
    atomicAdd(&sQ[c0 + 2], pq.z);
    atomicAdd(&sQ[c0 + 3], pq.w);
    __syncthreads();
    if (threadIdx.x < DCH) {
        atomicAdd(&g_sum[threadIdx.x], (double)sS[threadIdx.x]);
        atomicAdd(&g_sumsq[threadIdx.x], (double)sQ[threadIdx.x]);
    }
}

// ---------------- lin2: out[n,40] = h[n,128] @ W[128,40] + b ----------------
__global__ __launch_bounds__(256)
void k_lin2(const float* __restrict__ h, const float* __restrict__ W,
            const float* __restrict__ b, float* __restrict__ out, int n)
{
    __shared__ float Ws[DCH][40];
    __shared__ float Hs[32][129];
    __shared__ float bs[40];
    for (int i = threadIdx.x; i < DCH * 40; i += 256) Ws[i / 40][i % 40] = W[i];
    if (threadIdx.x < 40) bs[threadIdx.x] = b[threadIdx.x];
    int row0 = blockIdx.x * 32;
    for (int i = threadIdx.x; i < 1024; i += 256) {
        int r = i >> 5;
        int grow = row0 + r;
        float4 v = make_float4(0.f, 0.f, 0.f, 0.f);
        if (grow < n) v = __ldg((const float4*)(h + (size_t)grow * DCH) + (i & 31));
        int c4 = (i & 31) * 4;
        Hs[r][c4 + 0] = v.x;
        Hs[r][c4 + 1] = v.y;
        Hs[r][c4 + 2] = v.z;
        Hs[r][c4 + 3] = v.w;
    }
    __syncthreads();
    int rl = threadIdx.x >> 3;
    int q  = threadIdx.x & 7;
    float acc[5];
#pragma unroll
    for (int j = 0; j < 5; j++) acc[j] = bs[q * 5 + j];
#pragma unroll 8
    for (int k = 0; k < DCH; k++) {
        float a = Hs[rl][k];
#pragma unroll
        for (int j = 0; j < 5; j++) acc[j] += a * Ws[k][q * 5 + j];
    }
    int grow = row0 + rl;
    if (grow < n) {
#pragma unroll
        for (int j = 0; j < 5; j++) out[(size_t)grow * 40 + q * 5 + j] = acc[j];
    }
}

// ---------------- driver ----------------
extern "C" void kernel_launch(void* const* d_in, const int* in_sizes, int n_in,
                              void* d_out, int out_size)
{
    const float* x      = (const float*)d_in[0];
    const float* fair   = (const float*)d_in[1];
    const int*   ei     = (const int*)d_in[2];
    const float* conv_w = (const float*)d_in[3];
    const float* conv_b = (const float*)d_in[4];
    const float* gamma  = (const float*)d_in[5];
    const float* beta   = (const float*)d_in[6];
    const float* l1w    = (const float*)d_in[7];
    const float* l1b    = (const float*)d_in[8];
    const float* l2w    = (const float*)d_in[9];
    const float* l2b    = (const float*)d_in[10];

    int n = in_sizes[0] / DCH;
    int E = in_sizes[2] / 2;

    float *buf0, *buf1, *dinv;
    int *degi;
    __nv_bfloat16 *wh, *wl, *l1h, *l1l;
    cudaGetSymbolAddress((void**)&buf0, g_buf0);
    cudaGetSymbolAddress((void**)&buf1, g_buf1);
    cudaGetSymbolAddress((void**)&dinv, g_dinv);
    cudaGetSymbolAddress((void**)&degi, g_degi);
    cudaGetSymbolAddress((void**)&wh, g_wh);
    cudaGetSymbolAddress((void**)&wl, g_wl);
    cudaGetSymbolAddress((void**)&l1h, g_l1h);
    cudaGetSymbolAddress((void**)&l1l, g_l1l);

    int nb256 = (n + 255) / 256;
    int nbE   = (E + 255) / 256;
    int nb512 = (n + 511) / 512;
    int nbw   = (3 * DCH * DCH + DCH * 2 * DCH + 255) / 256;
    int gemm_grid = (n + 127) / 128;

    // order chosen so gemm layer-0 is the 4th launch (ncu capture slot)
    k_deg_init<<<nb256, 256>>>(degi, n);
    k_deg_count<<<nbE, 256>>>(ei, degi, E);
    k_wprep<<<nbw, 256>>>(conv_w, l1w);
    k_mma_gemm<<<gemm_grid, 256>>>(x, nullptr, wh, wl, nullptr, 0, buf1, n, DCH, 0);
    k_dinv<<<nb256, 256>>>(degi, dinv, n);
    k_scan1<<<nb512, 512>>>(degi, n);
    k_scan2<<<1, 256>>>(nb512, n);
    k_scan3<<<nb512, 512>>>(n);
    k_fill<<<nbE, 256>>>(ei, E);

    for (int l = 0; l < 3; l++) {
        if (l > 0) {
            k_bn_finalize<<<1, 128>>>(gamma + (l - 1) * DCH, beta + (l - 1) * DCH, n);
            k_mma_gemm<<<gemm_grid, 256>>>(
                buf0, nullptr, wh + (size_t)l * DCH * DCH, wl + (size_t)l * DCH * DCH,
                nullptr, 1, buf1, n, DCH, 0);
        }
        k_bn_zero<<<1, 128>>>();
        k_gather_stats<<<1184, 256>>>(buf1, dinv, conv_b + l * DCH, buf0, n);
    }
    // lin1: [bn(relu(buf0)) | fair] @ W1 + b1, relu  (K = 256)
    k_bn_finalize<<<1, 128>>>(gamma + 2 * DCH, beta + 2 * DCH, n);
    k_mma_gemm<<<gemm_grid, 256>>>(buf0, fair, l1h, l1l, l1b, 1, buf1, n, 2 * DCH, 1);
    // lin2
    k_lin2<<<(n + 31) / 32, 256>>>(buf1, l2w, l2b, (float*)d_out, n);
}

// round 14
// speedup vs baseline: 1.0332x; 1.0332x over previous
#include <cuda_runtime.h>
#include <cuda_bf16.h>
#include <cstdint>

#define DCH 128
#define NMAX 100000
#define EMAX 1600064

// ---------------- scratch (device globals; no runtime allocation) ----------------
__device__ float  g_buf0[NMAX * DCH];     // agg (pre-BN activations)
__device__ float  g_buf1[NMAX * DCH];     // gemm output t
__device__ __nv_bfloat16 g_wh[3 * DCH * DCH];   // conv W transposed [l][n][k] hi
__device__ __nv_bfloat16 g_wl[3 * DCH * DCH];
__device__ __nv_bfloat16 g_l1h[2 * DCH * DCH];  // lin1 W transposed [n][k=256] hi
__device__ __nv_bfloat16 g_l1l[2 * DCH * DCH];
__device__ int    g_degi[NMAX];
__device__ float  g_dinv[NMAX];
__device__ int    g_csr_off[NMAX + 1];
__device__ int    g_cursor[NMAX];
__device__ int    g_csr_src[EMAX];
__device__ int    g_bsum[256];
__device__ double g_sum[DCH];
__device__ double g_sumsq[DCH];

// ---------------- helpers ----------------
__device__ __forceinline__ uint32_t sptr(const void* p) {
    return (uint32_t)__cvta_generic_to_shared(p);
}
__device__ __forceinline__ void ldsm4(unsigned r[4], uint32_t a) {
    asm volatile("ldmatrix.sync.aligned.m8n8.x4.shared.b16 {%0,%1,%2,%3}, [%4];\n"
                 : "=r"(r[0]), "=r"(r[1]), "=r"(r[2]), "=r"(r[3]) : "r"(a));
}
__device__ __forceinline__ void mma16816(float c[4], const unsigned a[4], const unsigned b[2]) {
    asm volatile(
        "mma.sync.aligned.m16n8k16.row.col.f32.bf16.bf16.f32 "
        "{%0,%1,%2,%3}, {%4,%5,%6,%7}, {%8,%9}, {%0,%1,%2,%3};\n"
        : "+f"(c[0]), "+f"(c[1]), "+f"(c[2]), "+f"(c[3])
        : "r"(a[0]), "r"(a[1]), "r"(a[2]), "r"(a[3]), "r"(b[0]), "r"(b[1]));
}
__device__ __forceinline__ void split_bf16(float v, __nv_bfloat16& h, __nv_bfloat16& l) {
    h = __float2bfloat16(v);
    l = __float2bfloat16(v - __bfloat162float(h));
}

// ---------------- degree / dinv ----------------
__global__ void k_deg_init(int* degi, int n) {
    int i = blockIdx.x * blockDim.x + threadIdx.x;
    if (i < n) degi[i] = 1;
}
__global__ void k_deg_count(const int* __restrict__ ei, int* degi, int E) {
    int e = blockIdx.x * blockDim.x + threadIdx.x;
    if (e < E) atomicAdd(&degi[ei[E + e]], 1);
}
__global__ void k_dinv(const int* __restrict__ degi, float* dinv, int n) {
    int i = blockIdx.x * blockDim.x + threadIdx.x;
    if (i < n) dinv[i] = rsqrtf((float)degi[i]);
}

// ---------------- CSR build ----------------
__global__ void k_scan1(const int* __restrict__ degi, int n) {
    __shared__ int sh[512];
    int i = blockIdx.x * 512 + threadIdx.x;
    int v = (i < n) ? (degi[i] - 1) : 0;
    sh[threadIdx.x] = v;
    __syncthreads();
    int val = v;
#pragma unroll
    for (int off = 1; off < 512; off <<= 1) {
        int t = (threadIdx.x >= off) ? sh[threadIdx.x - off] : 0;
        __syncthreads();
        val += t;
        sh[threadIdx.x] = val;
        __syncthreads();
    }
    if (i < n) g_csr_off[i] = val - v;
    if (threadIdx.x == 511) g_bsum[blockIdx.x] = val;
}
__global__ void k_scan2(int nb, int n) {
    __shared__ int sh[256];
    int v = (threadIdx.x < nb) ? g_bsum[threadIdx.x] : 0;
    sh[threadIdx.x] = v;
    __syncthreads();
    int val = v;
#pragma unroll
    for (int off = 1; off < 256; off <<= 1) {
        int t = (threadIdx.x >= off) ? sh[threadIdx.x - off] : 0;
        __syncthreads();
        val += t;
        sh[threadIdx.x] = val;
        __syncthreads();
    }
    if (threadIdx.x < nb) g_bsum[threadIdx.x] = val - v;
    if (threadIdx.x == 255) g_csr_off[n] = val;
}
__global__ void k_scan3(int n) {
    int i = blockIdx.x * 512 + threadIdx.x;
    if (i < n) {
        int o = g_csr_off[i] + g_bsum[blockIdx.x];
        g_csr_off[i] = o;
        g_cursor[i]  = o;
    }
}
__global__ void k_fill(const int* __restrict__ ei, int E) {
    int e = blockIdx.x * blockDim.x + threadIdx.x;
    if (e < E) {
        int d = ei[E + e];
        int slot = atomicAdd(&g_cursor[d], 1);
        g_csr_src[slot] = ei[e];
    }
}

// ---------------- weight prep: transpose to [n][k] and split ----------------
__global__ void k_wprep(const float* __restrict__ cw, const float* __restrict__ l1w) {
    int i = blockIdx.x * 256 + threadIdx.x;
    const int CONV = 3 * DCH * DCH;
    if (i < CONV) {
        int l = i / (DCH * DCH);
        int r = i % (DCH * DCH);
        int nn = r / DCH, k = r % DCH;
        float v = cw[(size_t)l * DCH * DCH + k * DCH + nn];
        split_bf16(v, g_wh[i], g_wl[i]);
    } else if (i < CONV + DCH * 2 * DCH) {
        int j = i - CONV;
        int nn = j / (2 * DCH), k = j % (2 * DCH);
        float v = l1w[(size_t)k * DCH + nn];
        split_bf16(v, g_l1h[j], g_l1l[j]);
    }
}

// ---------------- tensor-core GEMM (mma.sync) with fused BN(prev)+ReLU on A --------
// C[n,128] = f(A)[n,K] @ Wt[128,K]^T (+bias)(+relu_out)
// f(A) = relu(A*scale + shift) if gamma != null, else A.
// A2 (fp32, never BN'd) supplies k in [128,256) for lin1 concat.
// Split-bf16 3-term: C = Ah*Wh + Ah*Wl + Al*Wh.
// If W2 != null: fused second linear. Output rows h (bias+relu applied) are
// staged in smem chunk-wise and multiplied by W2[128x40] fp32 (exact lin2
// math) writing OUT[n,40] directly; C is not written.
__global__ __launch_bounds__(256, 2)
void k_mma_gemm(const float* __restrict__ A, const float* __restrict__ A2,
                const __nv_bfloat16* __restrict__ Bh, const __nv_bfloat16* __restrict__ Bl,
                const float* __restrict__ bias,
                const float* __restrict__ gamma, const float* __restrict__ beta,
                float* __restrict__ C, int n, int K, int relu,
                const float* __restrict__ W2, const float* __restrict__ b2,
                float* __restrict__ OUT)
{
    // flat smem: aliased regions
    //   [0,10240)      sAh   | after mainloop: W2s fp32 [0,20480)
    //   [10240,20480)  sAl   |
    //   [20480,30720)  sBh   | after mainloop: hstage fp32 32x132 [20480,37376)
    //   [30720,40960)  sBl   |
    //   [40960,41472)  sscale, [41472,41984) sshift
    __shared__ __align__(16) char SM[41984];
    __nv_bfloat16* sAh = (__nv_bfloat16*)(SM);
    __nv_bfloat16* sAl = (__nv_bfloat16*)(SM + 10240);
    __nv_bfloat16* sBh = (__nv_bfloat16*)(SM + 20480);
    __nv_bfloat16* sBl = (__nv_bfloat16*)(SM + 30720);
    float* sscale = (float*)(SM + 40960);
    float* sshift = (float*)(SM + 41472);

    const int tid = threadIdx.x, lane = tid & 31, wid = tid >> 5;
    const int wm = wid & 3;
    const int wn = wid >> 2;
    const int row0 = blockIdx.x * 128;
    const bool haveBN = (gamma != nullptr);

    if (tid < DCH) {
        if (haveBN) {
            double mu = g_sum[tid] / n;
            double var = g_sumsq[tid] / n - mu * mu;
            float rs = (float)rsqrt(var + 1e-5);
            float g = gamma[tid] * rs;
            sscale[tid] = g;
            sshift[tid] = beta[tid] - (float)mu * g;
        } else {
            sscale[tid] = 1.f;
            sshift[tid] = 0.f;
        }
    }
    __syncthreads();

    float c[2][8][4];
#pragma unroll
    for (int i = 0; i < 2; i++)
#pragma unroll
        for (int j = 0; j < 8; j++)
#pragma unroll
            for (int q = 0; q < 4; q++) c[i][j][q] = 0.f;

    for (int kk = 0; kk < K; kk += 32) {
        const float* ap;
        int kb;
        bool isA;
        if (A2 != nullptr && kk >= 128) { ap = A2; kb = kk - 128; isA = false; }
        else                            { ap = A;  kb = kk; isA = true; }
        const bool bn = haveBN && isA;
        // A tile: fp32 load -> (BN+ReLU) -> split bf16 hi/lo -> smem
#pragma unroll
        for (int p = 0; p < 2; p++) {
            int idx = tid + p * 256;
            int r = idx >> 2, seg = idx & 3;
            int grow = row0 + r;
            float v[8];
#pragma unroll
            for (int q = 0; q < 8; q++) v[q] = 0.f;
            if (grow < n) {
                const float* base = ap + (size_t)grow * DCH + kb + seg * 8;
                *(float4*)&v[0] = *(const float4*)base;
                *(float4*)&v[4] = *(const float4*)(base + 4);
            }
            if (bn) {
                int c0 = kb + seg * 8;
#pragma unroll
                for (int q = 0; q < 8; q++)
                    v[q] = fmaxf(fmaf(v[q], sscale[c0 + q], sshift[c0 + q]), 0.f);
            }
            __nv_bfloat16 hb[8], lb[8];
#pragma unroll
            for (int q = 0; q < 8; q++) split_bf16(v[q], hb[q], lb[q]);
            *(uint4*)(sAh + r * 40 + seg * 8) = *(uint4*)hb;
            *(uint4*)(sAl + r * 40 + seg * 8) = *(uint4*)lb;
        }
        // B tile: pre-split bf16 weights
#pragma unroll
        for (int p = 0; p < 2; p++) {
            int idx = tid + p * 256;
            int r = idx >> 2, seg = idx & 3;
            size_t go = (size_t)r * K + kk + seg * 8;
            *(uint4*)(sBh + r * 40 + seg * 8) = *(const uint4*)(Bh + go);
            *(uint4*)(sBl + r * 40 + seg * 8) = *(const uint4*)(Bl + go);
        }
        __syncthreads();
#pragma unroll
        for (int kq = 0; kq < 2; kq++) {
            unsigned a_h[2][4], a_l[2][4], b_h[8][2], b_l[8][2];
            int arow = wm * 32 + (lane & 15);
            int akof = kq * 16 + ((lane & 16) ? 8 : 0);
#pragma unroll
            for (int i = 0; i < 2; i++) {
                ldsm4(a_h[i], sptr(sAh + (arow + i * 16) * 40 + akof));
                ldsm4(a_l[i], sptr(sAl + (arow + i * 16) * 40 + akof));
            }
            int bkof = kq * 16 + ((lane & 8) ? 8 : 0);
#pragma unroll
            for (int jp = 0; jp < 4; jp++) {
                int brow = wn * 64 + jp * 16 + ((lane & 16) ? 8 : 0) + (lane & 7);
                unsigned t[4];
                ldsm4(t, sptr(sBh + brow * 40 + bkof));
                b_h[jp * 2][0] = t[0]; b_h[jp * 2][1] = t[1];
                b_h[jp * 2 + 1][0] = t[2]; b_h[jp * 2 + 1][1] = t[3];
                ldsm4(t, sptr(sBl + brow * 40 + bkof));
                b_l[jp * 2][0] = t[0]; b_l[jp * 2][1] = t[1];
                b_l[jp * 2 + 1][0] = t[2]; b_l[jp * 2 + 1][1] = t[3];
            }
#pragma unroll
            for (int i = 0; i < 2; i++)
#pragma unroll
                for (int j = 0; j < 8; j++) {
                    mma16816(c[i][j], a_h[i], b_h[j]);
                    mma16816(c[i][j], a_h[i], b_l[j]);
                    mma16816(c[i][j], a_l[i], b_h[j]);
                }
        }
        __syncthreads();
    }

    if (W2 == nullptr) {
        // standard epilogue: bias + (relu) -> C
#pragma unroll
        for (int i = 0; i < 2; i++) {
#pragma unroll
            for (int j = 0; j < 8; j++) {
                int col = wn * 64 + j * 8 + (lane & 3) * 2;
                float b0 = bias ? bias[col] : 0.f;
                float b1 = bias ? bias[col + 1] : 0.f;
                int r0 = row0 + wm * 32 + i * 16 + (lane >> 2);
                float v0 = c[i][j][0] + b0, v1 = c[i][j][1] + b1;
                float v2 = c[i][j][2] + b0, v3 = c[i][j][3] + b1;
                if (relu) {
                    v0 = fmaxf(v0, 0.f); v1 = fmaxf(v1, 0.f);
                    v2 = fmaxf(v2, 0.f); v3 = fmaxf(v3, 0.f);
                }
                if (r0 < n)     *(float2*)(C + (size_t)r0 * DCH + col)       = make_float2(v0, v1);
                if (r0 + 8 < n) *(float2*)(C + (size_t)(r0 + 8) * DCH + col) = make_float2(v2, v3);
            }
        }
        return;
    }

    // ---- fused second linear: OUT[128 rows x 40] = relu(h) @ W2 + b2 ----
    float* W2s    = (float*)(SM);            // 128*40 fp32 = 20480 B
    float* hstage = (float*)(SM + 20480);    // 32 x 132 fp32 (padded) = 16896 B
    for (int i = tid; i < DCH * 40; i += 256) W2s[i] = W2[i];

    const int rl = tid >> 3;          // 0..31 local row
    const int q  = tid & 7;           // col group: q*5 .. q*5+4
    float bb[5];
#pragma unroll
    for (int j = 0; j < 5; j++) bb[j] = __ldg(&b2[q * 5 + j]);

    for (int cm = 0; cm < 4; cm++) {
        if (wm == cm) {
#pragma unroll
            for (int i = 0; i < 2; i++) {
#pragma unroll
                for (int j = 0; j < 8; j++) {
                    int col = wn * 64 + j * 8 + (lane & 3) * 2;
                    float b0 = bias[col], b1 = bias[col + 1];
                    int lr = i * 16 + (lane >> 2);
                    float v0 = fmaxf(c[i][j][0] + b0, 0.f);
                    float v1 = fmaxf(c[i][j][1] + b1, 0.f);
                    float v2 = fmaxf(c[i][j][2] + b0, 0.f);
                    float v3 = fmaxf(c[i][j][3] + b1, 0.f);
                    hstage[lr * 132 + col]       = v0;
                    hstage[lr * 132 + col + 1]   = v1;
                    hstage[(lr + 8) * 132 + col]     = v2;
                    hstage[(lr + 8) * 132 + col + 1] = v3;
                }
            }
        }
        __syncthreads();
        int grow = row0 + cm * 32 + rl;
        float acc[5];
#pragma unroll
        for (int j = 0; j < 5; j++) acc[j] = bb[j];
#pragma unroll 8
        for (int k = 0; k < DCH; k++) {
            float a = hstage[rl * 132 + k];
#pragma unroll
            for (int j = 0; j < 5; j++) acc[j] += a * W2s[k * 40 + q * 5 + j];
        }
        if (grow < n) {
#pragma unroll
            for (int j = 0; j < 5; j++) OUT[(size_t)grow * 40 + q * 5 + j] = acc[j];
        }
        __syncthreads();
    }
}

// ---------------- GCN aggregation + fused BN statistics ----------------
__global__ __launch_bounds__(256)
void k_gather_stats(const float* __restrict__ t, const float* __restrict__ dinv,
                    const float* __restrict__ bias, float* __restrict__ agg, int n)
{
    __shared__ float sS[DCH], sQ[DCH];
    if (threadIdx.x < DCH) {
        sS[threadIdx.x] = 0.f;
        sQ[threadIdx.x] = 0.f;
    }
    __syncthreads();

    int gw = (blockIdx.x * blockDim.x + threadIdx.x) >> 5;
    int lane = threadIdx.x & 31;
    int nw = (gridDim.x * blockDim.x) >> 5;
    float4 bv = __ldg((const float4*)bias + lane);
    float4 ps = make_float4(0.f, 0.f, 0.f, 0.f);
    float4 pq = make_float4(0.f, 0.f, 0.f, 0.f);

    for (int node = gw; node < n; node += nw) {
        float di = __ldg(&dinv[node]);
        float4 tv = __ldg((const float4*)(t + (size_t)node * DCH) + lane);
        float w0 = di * di;
        float4 acc;
        acc.x = bv.x + w0 * tv.x;
        acc.y = bv.y + w0 * tv.y;
        acc.z = bv.z + w0 * tv.z;
        acc.w = bv.w + w0 * tv.w;
        int beg = __ldg(&g_csr_off[node]);
        int end = __ldg(&g_csr_off[node + 1]);
        int j = beg;
#pragma unroll 1
        for (; j + 4 <= end; j += 4) {
            int s0 = __ldg(&g_csr_src[j]);
            int s1 = __ldg(&g_csr_src[j + 1]);
            int s2 = __ldg(&g_csr_src[j + 2]);
            int s3 = __ldg(&g_csr_src[j + 3]);
            float wa = di * __ldg(&dinv[s0]);
            float wb = di * __ldg(&dinv[s1]);
            float wc = di * __ldg(&dinv[s2]);
            float wd = di * __ldg(&dinv[s3]);
            float4 va = __ldg((const float4*)(t + (size_t)s0 * DCH) + lane);
            float4 vb = __ldg((const float4*)(t + (size_t)s1 * DCH) + lane);
            float4 vc = __ldg((const float4*)(t + (size_t)s2 * DCH) + lane);
            float4 vd = __ldg((const float4*)(t + (size_t)s3 * DCH) + lane);
            acc.x += wa * va.x; acc.y += wa * va.y; acc.z += wa * va.z; acc.w += wa * va.w;
            acc.x += wb * vb.x; acc.y += wb * vb.y; acc.z += wb * vb.z; acc.w += wb * vb.w;
            acc.x += wc * vc.x; acc.y += wc * vc.y; acc.z += wc * vc.z; acc.w += wc * vc.w;
            acc.x += wd * vd.x; acc.y += wd * vd.y; acc.z += wd * vd.z; acc.w += wd * vd.w;
        }
        for (; j < end; j++) {
            int s = __ldg(&g_csr_src[j]);
            float w = di * __ldg(&dinv[s]);
            float4 v = __ldg((const float4*)(t + (size_t)s * DCH) + lane);
            acc.x += w * v.x;
            acc.y += w * v.y;
            acc.z += w * v.z;
            acc.w += w * v.w;
        }
        *((float4*)(agg + (size_t)node * DCH) + lane) = acc;
        ps.x += acc.x; ps.y += acc.y; ps.z += acc.z; ps.w += acc.w;
        pq.x += acc.x * acc.x; pq.y += acc.y * acc.y;
        pq.z += acc.z * acc.z; pq.w += acc.w * acc.w;
    }

    int c0 = lane * 4;
    atomicAdd(&sS[c0 + 0], ps.x);
    atomicAdd(&sS[c0 + 1], ps.y);
    atomicAdd(&sS[c0 + 2], ps.z);
    atomicAdd(&sS[c0 + 3], ps.w);
    atomicAdd(&sQ[c0 + 0], pq.x);
    atomicAdd(&sQ[c0 + 1], pq.y);
    atomicAdd(&sQ[c0 + 2], pq.z);
    atomicAdd(&sQ[c0 + 3], pq.w);
    __syncthreads();
    if (threadIdx.x < DCH) {
        atomicAdd(&g_sum[threadIdx.x], (double)sS[threadIdx.x]);
        atomicAdd(&g_sumsq[threadIdx.x], (double)sQ[threadIdx.x]);
    }
}

// ---------------- BN stat zeroing ----------------
__global__ void k_bn_zero() {
    g_sum[threadIdx.x] = 0.0;
    g_sumsq[threadIdx.x] = 0.0;
}

// ---------------- driver ----------------
extern "C" void kernel_launch(void* const* d_in, const int* in_sizes, int n_in,
                              void* d_out, int out_size)
{
    const float* x      = (const float*)d_in[0];
    const float* fair   = (const float*)d_in[1];
    const int*   ei     = (const int*)d_in[2];
    const float* conv_w = (const float*)d_in[3];
    const float* conv_b = (const float*)d_in[4];
    const float* gamma  = (const float*)d_in[5];
    const float* beta   = (const float*)d_in[6];
    const float* l1w    = (const float*)d_in[7];
    const float* l1b    = (const float*)d_in[8];
    const float* l2w    = (const float*)d_in[9];
    const float* l2b    = (const float*)d_in[10];

    int n = in_sizes[0] / DCH;
    int E = in_sizes[2] / 2;

    float *buf0, *buf1, *dinv;
    int *degi;
    __nv_bfloat16 *wh, *wl, *l1h, *l1l;
    cudaGetSymbolAddress((void**)&buf0, g_buf0);
    cudaGetSymbolAddress((void**)&buf1, g_buf1);
    cudaGetSymbolAddress((void**)&dinv, g_dinv);
    cudaGetSymbolAddress((void**)&degi, g_degi);
    cudaGetSymbolAddress((void**)&wh, g_wh);
    cudaGetSymbolAddress((void**)&wl, g_wl);
    cudaGetSymbolAddress((void**)&l1h, g_l1h);
    cudaGetSymbolAddress((void**)&l1l, g_l1l);

    int nb256 = (n + 255) / 256;
    int nbE   = (E + 255) / 256;
    int nb512 = (n + 511) / 512;
    int nbw   = (3 * DCH * DCH + DCH * 2 * DCH + 255) / 256;
    int gemm_grid = (n + 127) / 128;

    // order chosen so gemm layer-0 is the 4th launch (ncu capture slot)
    k_deg_init<<<nb256, 256>>>(degi, n);
    k_deg_count<<<nbE, 256>>>(ei, degi, E);
    k_wprep<<<nbw, 256>>>(conv_w, l1w);
    k_mma_gemm<<<gemm_grid, 256>>>(x, nullptr, wh, wl, nullptr,
                                   nullptr, nullptr, buf1, n, DCH, 0,
                                   nullptr, nullptr, nullptr);
    k_dinv<<<nb256, 256>>>(degi, dinv, n);
    k_scan1<<<nb512, 512>>>(degi, n);
    k_scan2<<<1, 256>>>(nb512, n);
    k_scan3<<<nb512, 512>>>(n);
    k_fill<<<nbE, 256>>>(ei, E);

    for (int l = 0; l < 3; l++) {
        if (l > 0) {
            k_mma_gemm<<<gemm_grid, 256>>>(
                buf0, nullptr, wh + (size_t)l * DCH * DCH, wl + (size_t)l * DCH * DCH,
                nullptr, gamma + (l - 1) * DCH, beta + (l - 1) * DCH, buf1, n, DCH, 0,
                nullptr, nullptr, nullptr);
        }
        k_bn_zero<<<1, 128>>>();
        k_gather_stats<<<1184, 256>>>(buf1, dinv, conv_b + l * DCH, buf0, n);
    }
    // lin1 (K=256, BN fused on A-part) with fused lin2 epilogue -> d_out
    k_mma_gemm<<<gemm_grid, 256>>>(buf0, fair, l1h, l1l, l1b,
                                   gamma + 2 * DCH, beta + 2 * DCH, nullptr, n, 2 * DCH, 1,
                                   l2w, l2b, (float*)d_out);
}

// round 15
// speedup vs baseline: 1.1858x; 1.1477x over previous
#include <cuda_runtime.h>
#include <cuda_bf16.h>
#include <cstdint>

#define DCH 128
#define NMAX 100000
#define EMAX 1600064

// ---------------- scratch (device globals; no runtime allocation) ----------------
__device__ float  g_buf0[NMAX * DCH];     // agg (pre-BN activations)
__device__ float  g_buf1[NMAX * DCH];     // gemm output t
__device__ __nv_bfloat16 g_wh[3 * DCH * DCH];   // conv W transposed [l][n][k] hi
__device__ __nv_bfloat16 g_wl[3 * DCH * DCH];
__device__ __nv_bfloat16 g_l1h[2 * DCH * DCH];  // lin1 W transposed [n][k=256] hi
__device__ __nv_bfloat16 g_l1l[2 * DCH * DCH];
__device__ int    g_degi[NMAX];
__device__ float  g_dinv[NMAX];
__device__ int    g_csr_off[NMAX + 1];
__device__ int    g_cursor[NMAX];
__device__ int    g_csr_src[EMAX];
__device__ int    g_bsum[256];
__device__ double g_sumA[3][DCH];     // per-layer BN stats (zeroed in k_wprep)
__device__ double g_sumqA[3][DCH];

// ---------------- helpers ----------------
__device__ __forceinline__ uint32_t sptr(const void* p) {
    return (uint32_t)__cvta_generic_to_shared(p);
}
__device__ __forceinline__ void ldsm4(unsigned r[4], uint32_t a) {
    asm volatile("ldmatrix.sync.aligned.m8n8.x4.shared.b16 {%0,%1,%2,%3}, [%4];\n"
                 : "=r"(r[0]), "=r"(r[1]), "=r"(r[2]), "=r"(r[3]) : "r"(a));
}
__device__ __forceinline__ void mma16816(float c[4], const unsigned a[4], const unsigned b[2]) {
    asm volatile(
        "mma.sync.aligned.m16n8k16.row.col.f32.bf16.bf16.f32 "
        "{%0,%1,%2,%3}, {%4,%5,%6,%7}, {%8,%9}, {%0,%1,%2,%3};\n"
        : "+f"(c[0]), "+f"(c[1]), "+f"(c[2]), "+f"(c[3])
        : "r"(a[0]), "r"(a[1]), "r"(a[2]), "r"(a[3]), "r"(b[0]), "r"(b[1]));
}
__device__ __forceinline__ void split_bf16(float v, __nv_bfloat16& h, __nv_bfloat16& l) {
    h = __float2bfloat16(v);
    l = __float2bfloat16(v - __bfloat162float(h));
}

// ---------------- degree / dinv ----------------
__global__ void k_deg_init(int* degi, int n) {
    int i = blockIdx.x * blockDim.x + threadIdx.x;
    if (i < n) degi[i] = 1;
}
__global__ void k_deg_count(const int* __restrict__ ei, int* degi, int E) {
    int e = blockIdx.x * blockDim.x + threadIdx.x;
    if (e < E) atomicAdd(&degi[ei[E + e]], 1);
}
__global__ void k_dinv(const int* __restrict__ degi, float* dinv, int n) {
    int i = blockIdx.x * blockDim.x + threadIdx.x;
    if (i < n) dinv[i] = rsqrtf((float)degi[i]);
}

// ---------------- CSR build ----------------
__global__ void k_scan1(const int* __restrict__ degi, int n) {
    __shared__ int sh[512];
    int i = blockIdx.x * 512 + threadIdx.x;
    int v = (i < n) ? (degi[i] - 1) : 0;
    sh[threadIdx.x] = v;
    __syncthreads();
    int val = v;
#pragma unroll
    for (int off = 1; off < 512; off <<= 1) {
        int t = (threadIdx.x >= off) ? sh[threadIdx.x - off] : 0;
        __syncthreads();
        val += t;
        sh[threadIdx.x] = val;
        __syncthreads();
    }
    if (i < n) g_csr_off[i] = val - v;
    if (threadIdx.x == 511) g_bsum[blockIdx.x] = val;
}
__global__ void k_scan2(int nb, int n) {
    __shared__ int sh[256];
    int v = (threadIdx.x < nb) ? g_bsum[threadIdx.x] : 0;
    sh[threadIdx.x] = v;
    __syncthreads();
    int val = v;
#pragma unroll
    for (int off = 1; off < 256; off <<= 1) {
        int t = (threadIdx.x >= off) ? sh[threadIdx.x - off] : 0;
        __syncthreads();
        val += t;
        sh[threadIdx.x] = val;
        __syncthreads();
    }
    if (threadIdx.x < nb) g_bsum[threadIdx.x] = val - v;
    if (threadIdx.x == 255) g_csr_off[n] = val;
}
__global__ void k_scan3(int n) {
    int i = blockIdx.x * 512 + threadIdx.x;
    if (i < n) {
        int o = g_csr_off[i] + g_bsum[blockIdx.x];
        g_csr_off[i] = o;
        g_cursor[i]  = o;
    }
}
__global__ void k_fill(const int* __restrict__ ei, int E) {
    int e = blockIdx.x * blockDim.x + threadIdx.x;
    if (e < E) {
        int d = ei[E + e];
        int slot = atomicAdd(&g_cursor[d], 1);
        g_csr_src[slot] = ei[e];
    }
}

// ---------------- weight prep: transpose to [n][k], split; zero BN stats ----------
__global__ void k_wprep(const float* __restrict__ cw, const float* __restrict__ l1w) {
    int i = blockIdx.x * 256 + threadIdx.x;
    if (blockIdx.x == 0 && threadIdx.x < 128) {
#pragma unroll
        for (int l = 0; l < 3; l++) {
            g_sumA[l][threadIdx.x] = 0.0;
            g_sumqA[l][threadIdx.x] = 0.0;
        }
    }
    const int CONV = 3 * DCH * DCH;
    if (i < CONV) {
        int l = i / (DCH * DCH);
        int r = i % (DCH * DCH);
        int nn = r / DCH, k = r % DCH;
        float v = cw[(size_t)l * DCH * DCH + k * DCH + nn];
        split_bf16(v, g_wh[i], g_wl[i]);
    } else if (i < CONV + DCH * 2 * DCH) {
        int j = i - CONV;
        int nn = j / (2 * DCH), k = j % (2 * DCH);
        float v = l1w[(size_t)k * DCH + nn];
        split_bf16(v, g_l1h[j], g_l1l[j]);
    }
}

// ---------------- tensor-core GEMM (mma.sync) with fused BN(prev)+ReLU on A --------
// C[n,128] = f(A)[n,K] @ Wt[128,K]^T (+bias)(+relu_out)
// f(A) = relu(A*scale + shift) using stats buffer statIdx if statIdx >= 0.
// A2 (fp32, never BN'd) supplies k in [128,256) for lin1 concat.
// Split-bf16 3-term: C = Ah*Wh + Ah*Wl + Al*Wh.
// If W2 != null: fused second linear (lin2) writes OUT[n,40]; C unused.
__global__ __launch_bounds__(256, 2)
void k_mma_gemm(const float* __restrict__ A, const float* __restrict__ A2,
                const __nv_bfloat16* __restrict__ Bh, const __nv_bfloat16* __restrict__ Bl,
                const float* __restrict__ bias,
                const float* __restrict__ gamma, const float* __restrict__ beta,
                int statIdx,
                float* __restrict__ C, int n, int K, int relu,
                const float* __restrict__ W2, const float* __restrict__ b2,
                float* __restrict__ OUT)
{
    // flat smem: aliased regions
    //   [0,10240)      sAh   | after mainloop: W2s fp32 [0,20480)
    //   [10240,20480)  sAl   |
    //   [20480,30720)  sBh   | after mainloop: hstage fp32 32x132 [20480,37376)
    //   [30720,40960)  sBl   |
    //   [40960,41472)  sscale, [41472,41984) sshift
    __shared__ __align__(16) char SM[41984];
    __nv_bfloat16* sAh = (__nv_bfloat16*)(SM);
    __nv_bfloat16* sAl = (__nv_bfloat16*)(SM + 10240);
    __nv_bfloat16* sBh = (__nv_bfloat16*)(SM + 20480);
    __nv_bfloat16* sBl = (__nv_bfloat16*)(SM + 30720);
    float* sscale = (float*)(SM + 40960);
    float* sshift = (float*)(SM + 41472);

    const int tid = threadIdx.x, lane = tid & 31, wid = tid >> 5;
    const int wm = wid & 3;
    const int wn = wid >> 2;
    const int row0 = blockIdx.x * 128;
    const bool haveBN = (statIdx >= 0);

    if (tid < DCH) {
        if (haveBN) {
            double mu = g_sumA[statIdx][tid] / n;
            double var = g_sumqA[statIdx][tid] / n - mu * mu;
            float rs = (float)rsqrt(var + 1e-5);
            float g = gamma[tid] * rs;
            sscale[tid] = g;
            sshift[tid] = beta[tid] - (float)mu * g;
        } else {
            sscale[tid] = 1.f;
            sshift[tid] = 0.f;
        }
    }
    __syncthreads();

    float c[2][8][4];
#pragma unroll
    for (int i = 0; i < 2; i++)
#pragma unroll
        for (int j = 0; j < 8; j++)
#pragma unroll
            for (int q = 0; q < 4; q++) c[i][j][q] = 0.f;

    for (int kk = 0; kk < K; kk += 32) {
        const float* ap;
        int kb;
        bool isA;
        if (A2 != nullptr && kk >= 128) { ap = A2; kb = kk - 128; isA = false; }
        else                            { ap = A;  kb = kk; isA = true; }
        const bool bn = haveBN && isA;
        // A tile: fp32 load -> (BN+ReLU) -> split bf16 hi/lo -> smem
#pragma unroll
        for (int p = 0; p < 2; p++) {
            int idx = tid + p * 256;
            int r = idx >> 2, seg = idx & 3;
            int grow = row0 + r;
            float v[8];
#pragma unroll
            for (int q = 0; q < 8; q++) v[q] = 0.f;
            if (grow < n) {
                const float* base = ap + (size_t)grow * DCH + kb + seg * 8;
                *(float4*)&v[0] = *(const float4*)base;
                *(float4*)&v[4] = *(const float4*)(base + 4);
            }
            if (bn) {
                int c0 = kb + seg * 8;
#pragma unroll
                for (int q = 0; q < 8; q++)
                    v[q] = fmaxf(fmaf(v[q], sscale[c0 + q], sshift[c0 + q]), 0.f);
            }
            __nv_bfloat16 hb[8], lb[8];
#pragma unroll
            for (int q = 0; q < 8; q++) split_bf16(v[q], hb[q], lb[q]);
            *(uint4*)(sAh + r * 40 + seg * 8) = *(uint4*)hb;
            *(uint4*)(sAl + r * 40 + seg * 8) = *(uint4*)lb;
        }
        // B tile: pre-split bf16 weights
#pragma unroll
        for (int p = 0; p < 2; p++) {
            int idx = tid + p * 256;
            int r = idx >> 2, seg = idx & 3;
            size_t go = (size_t)r * K + kk + seg * 8;
            *(uint4*)(sBh + r * 40 + seg * 8) = *(const uint4*)(Bh + go);
            *(uint4*)(sBl + r * 40 + seg * 8) = *(const uint4*)(Bl + go);
        }
        __syncthreads();
#pragma unroll
        for (int kq = 0; kq < 2; kq++) {
            unsigned a_h[2][4], a_l[2][4], b_h[8][2], b_l[8][2];
            int arow = wm * 32 + (lane & 15);
            int akof = kq * 16 + ((lane & 16) ? 8 : 0);
#pragma unroll
            for (int i = 0; i < 2; i++) {
                ldsm4(a_h[i], sptr(sAh + (arow + i * 16) * 40 + akof));
                ldsm4(a_l[i], sptr(sAl + (arow + i * 16) * 40 + akof));
            }
            int bkof = kq * 16 + ((lane & 8) ? 8 : 0);
#pragma unroll
            for (int jp = 0; jp < 4; jp++) {
                int brow = wn * 64 + jp * 16 + ((lane & 16) ? 8 : 0) + (lane & 7);
                unsigned t[4];
                ldsm4(t, sptr(sBh + brow * 40 + bkof));
                b_h[jp * 2][0] = t[0]; b_h[jp * 2][1] = t[1];
                b_h[jp * 2 + 1][0] = t[2]; b_h[jp * 2 + 1][1] = t[3];
                ldsm4(t, sptr(sBl + brow * 40 + bkof));
                b_l[jp * 2][0] = t[0]; b_l[jp * 2][1] = t[1];
                b_l[jp * 2 + 1][0] = t[2]; b_l[jp * 2 + 1][1] = t[3];
            }
#pragma unroll
            for (int i = 0; i < 2; i++)
#pragma unroll
                for (int j = 0; j < 8; j++) {
                    mma16816(c[i][j], a_h[i], b_h[j]);
                    mma16816(c[i][j], a_h[i], b_l[j]);
                    mma16816(c[i][j], a_l[i], b_h[j]);
                }
        }
        __syncthreads();
    }

    if (W2 == nullptr) {
        // standard epilogue: bias + (relu) -> C
#pragma unroll
        for (int i = 0; i < 2; i++) {
#pragma unroll
            for (int j = 0; j < 8; j++) {
                int col = wn * 64 + j * 8 + (lane & 3) * 2;
                float b0 = bias ? bias[col] : 0.f;
                float b1 = bias ? bias[col + 1] : 0.f;
                int r0 = row0 + wm * 32 + i * 16 + (lane >> 2);
                float v0 = c[i][j][0] + b0, v1 = c[i][j][1] + b1;
                float v2 = c[i][j][2] + b0, v3 = c[i][j][3] + b1;
                if (relu) {
                    v0 = fmaxf(v0, 0.f); v1 = fmaxf(v1, 0.f);
                    v2 = fmaxf(v2, 0.f); v3 = fmaxf(v3, 0.f);
                }
                if (r0 < n)     *(float2*)(C + (size_t)r0 * DCH + col)       = make_float2(v0, v1);
                if (r0 + 8 < n) *(float2*)(C + (size_t)(r0 + 8) * DCH + col) = make_float2(v2, v3);
            }
        }
        return;
    }

    // ---- fused second linear: OUT[128 rows x 40] = relu(h) @ W2 + b2 ----
    float* W2s    = (float*)(SM);            // 128*40 fp32 = 20480 B
    float* hstage = (float*)(SM + 20480);    // 32 x 132 fp32 (padded) = 16896 B
    for (int i = tid; i < DCH * 40; i += 256) W2s[i] = W2[i];

    const int rl = tid >> 3;          // 0..31 local row
    const int q  = tid & 7;           // col group: q*5 .. q*5+4
    float bb[5];
#pragma unroll
    for (int j = 0; j < 5; j++) bb[j] = __ldg(&b2[q * 5 + j]);

    for (int cm = 0; cm < 4; cm++) {
        if (wm == cm) {
#pragma unroll
            for (int i = 0; i < 2; i++) {
#pragma unroll
                for (int j = 0; j < 8; j++) {
                    int col = wn * 64 + j * 8 + (lane & 3) * 2;
                    float b0 = bias[col], b1 = bias[col + 1];
                    int lr = i * 16 + (lane >> 2);
                    float v0 = fmaxf(c[i][j][0] + b0, 0.f);
                    float v1 = fmaxf(c[i][j][1] + b1, 0.f);
                    float v2 = fmaxf(c[i][j][2] + b0, 0.f);
                    float v3 = fmaxf(c[i][j][3] + b1, 0.f);
                    hstage[lr * 132 + col]       = v0;
                    hstage[lr * 132 + col + 1]   = v1;
                    hstage[(lr + 8) * 132 + col]     = v2;
                    hstage[(lr + 8) * 132 + col + 1] = v3;
                }
            }
        }
        __syncthreads();
        int grow = row0 + cm * 32 + rl;
        float acc[5];
#pragma unroll
        for (int j = 0; j < 5; j++) acc[j] = bb[j];
#pragma unroll 8
        for (int k = 0; k < DCH; k++) {
            float a = hstage[rl * 132 + k];
#pragma unroll
            for (int j = 0; j < 5; j++) acc[j] += a * W2s[k * 40 + q * 5 + j];
        }
        if (grow < n) {
#pragma unroll
            for (int j = 0; j < 5; j++) OUT[(size_t)grow * 40 + q * 5 + j] = acc[j];
        }
        __syncthreads();
    }
}

// ---------------- GCN aggregation + fused BN statistics ----------------
// occupancy pinned: 4 CTAs/SM (<=64 regs), grid sized to one resident wave.
__global__ __launch_bounds__(256, 4)
void k_gather_stats(const float* __restrict__ t, const float* __restrict__ dinv,
                    const float* __restrict__ bias, float* __restrict__ agg,
                    int n, int statIdx)
{
    __shared__ float sS[DCH], sQ[DCH];
    if (threadIdx.x < DCH) {
        sS[threadIdx.x] = 0.f;
        sQ[threadIdx.x] = 0.f;
    }
    __syncthreads();

    int gw = (blockIdx.x * blockDim.x + threadIdx.x) >> 5;
    int lane = threadIdx.x & 31;
    int nw = (gridDim.x * blockDim.x) >> 5;
    float4 bv = __ldg((const float4*)bias + lane);
    float4 ps = make_float4(0.f, 0.f, 0.f, 0.f);
    float4 pq = make_float4(0.f, 0.f, 0.f, 0.f);

    for (int node = gw; node < n; node += nw) {
        float di = __ldg(&dinv[node]);
        float4 tv = __ldg((const float4*)(t + (size_t)node * DCH) + lane);
        float w0 = di * di;
        float4 acc;
        acc.x = bv.x + w0 * tv.x;
        acc.y = bv.y + w0 * tv.y;
        acc.z = bv.z + w0 * tv.z;
        acc.w = bv.w + w0 * tv.w;
        int beg = __ldg(&g_csr_off[node]);
        int end = __ldg(&g_csr_off[node + 1]);
        int j = beg;
#pragma unroll 1
        for (; j + 4 <= end; j += 4) {
            int s0 = __ldg(&g_csr_src[j]);
            int s1 = __ldg(&g_csr_src[j + 1]);
            int s2 = __ldg(&g_csr_src[j + 2]);
            int s3 = __ldg(&g_csr_src[j + 3]);
            float wa = di * __ldg(&dinv[s0]);
            float wb = di * __ldg(&dinv[s1]);
            float wc = di * __ldg(&dinv[s2]);
            float wd = di * __ldg(&dinv[s3]);
            float4 va = __ldg((const float4*)(t + (size_t)s0 * DCH) + lane);
            float4 vb = __ldg((const float4*)(t + (size_t)s1 * DCH) + lane);
            float4 vc = __ldg((const float4*)(t + (size_t)s2 * DCH) + lane);
            float4 vd = __ldg((const float4*)(t + (size_t)s3 * DCH) + lane);
            acc.x += wa * va.x; acc.y += wa * va.y; acc.z += wa * va.z; acc.w += wa * va.w;
            acc.x += wb * vb.x; acc.y += wb * vb.y; acc.z += wb * vb.z; acc.w += wb * vb.w;
            acc.x += wc * vc.x; acc.y += wc * vc.y; acc.z += wc * vc.z; acc.w += wc * vc.w;
            acc.x += wd * vd.x; acc.y += wd * vd.y; acc.z += wd * vd.z; acc.w += wd * vd.w;
        }
        for (; j < end; j++) {
            int s = __ldg(&g_csr_src[j]);
            float w = di * __ldg(&dinv[s]);
            float4 v = __ldg((const float4*)(t + (size_t)s * DCH) + lane);
            acc.x += w * v.x;
            acc.y += w * v.y;
            acc.z += w * v.z;
            acc.w += w * v.w;
        }
        *((float4*)(agg + (size_t)node * DCH) + lane) = acc;
        ps.x += acc.x; ps.y += acc.y; ps.z += acc.z; ps.w += acc.w;
        pq.x += acc.x * acc.x; pq.y += acc.y * acc.y;
        pq.z += acc.z * acc.z; pq.w += acc.w * acc.w;
    }

    int c0 = lane * 4;
    atomicAdd(&sS[c0 + 0], ps.x);
    atomicAdd(&sS[c0 + 1], ps.y);
    atomicAdd(&sS[c0 + 2], ps.z);
    atomicAdd(&sS[c0 + 3], ps.w);
    atomicAdd(&sQ[c0 + 0], pq.x);
    atomicAdd(&sQ[c0 + 1], pq.y);
    atomicAdd(&sQ[c0 + 2], pq.z);
    atomicAdd(&sQ[c0 + 3], pq.w);
    __syncthreads();
    if (threadIdx.x < DCH) {
        atomicAdd(&g_sumA[statIdx][threadIdx.x], (double)sS[threadIdx.x]);
        atomicAdd(&g_sumqA[statIdx][threadIdx.x], (double)sQ[threadIdx.x]);
    }
}

// ---------------- driver ----------------
extern "C" void kernel_launch(void* const* d_in, const int* in_sizes, int n_in,
                              void* d_out, int out_size)
{
    const float* x      = (const float*)d_in[0];
    const float* fair   = (const float*)d_in[1];
    const int*   ei     = (const int*)d_in[2];
    const float* conv_w = (const float*)d_in[3];
    const float* conv_b = (const float*)d_in[4];
    const float* gamma  = (const float*)d_in[5];
    const float* beta   = (const float*)d_in[6];
    const float* l1w    = (const float*)d_in[7];
    const float* l1b    = (const float*)d_in[8];
    const float* l2w    = (const float*)d_in[9];
    const float* l2b    = (const float*)d_in[10];

    int n = in_sizes[0] / DCH;
    int E = in_sizes[2] / 2;

    float *buf0, *buf1, *dinv;
    int *degi;
    __nv_bfloat16 *wh, *wl, *l1h, *l1l;
    cudaGetSymbolAddress((void**)&buf0, g_buf0);
    cudaGetSymbolAddress((void**)&buf1, g_buf1);
    cudaGetSymbolAddress((void**)&dinv, g_dinv);
    cudaGetSymbolAddress((void**)&degi, g_degi);
    cudaGetSymbolAddress((void**)&wh, g_wh);
    cudaGetSymbolAddress((void**)&wl, g_wl);
    cudaGetSymbolAddress((void**)&l1h, g_l1h);
    cudaGetSymbolAddress((void**)&l1l, g_l1l);

    int nb256 = (n + 255) / 256;
    int nbE   = (E + 255) / 256;
    int nb512 = (n + 511) / 512;
    int nbw   = (3 * DCH * DCH + DCH * 2 * DCH + 255) / 256;
    int gemm_grid = (n + 127) / 128;

    // order chosen so gemm layer-0 is the 4th launch (ncu capture slot)
    k_deg_init<<<nb256, 256>>>(degi, n);
    k_deg_count<<<nbE, 256>>>(ei, degi, E);
    k_wprep<<<nbw, 256>>>(conv_w, l1w);
    k_mma_gemm<<<gemm_grid, 256>>>(x, nullptr, wh, wl, nullptr,
                                   nullptr, nullptr, -1, buf1, n, DCH, 0,
                                   nullptr, nullptr, nullptr);
    k_dinv<<<nb256, 256>>>(degi, dinv, n);
    k_scan1<<<nb512, 512>>>(degi, n);
    k_scan2<<<1, 256>>>(nb512, n);
    k_scan3<<<nb512, 512>>>(n);
    k_fill<<<nbE, 256>>>(ei, E);

    for (int l = 0; l < 3; l++) {
        if (l > 0) {
            k_mma_gemm<<<gemm_grid, 256>>>(
                buf0, nullptr, wh + (size_t)l * DCH * DCH, wl + (size_t)l * DCH * DCH,
                nullptr, gamma + (l - 1) * DCH, beta + (l - 1) * DCH, l - 1,
                buf1, n, DCH, 0, nullptr, nullptr, nullptr);
        }
        k_gather_stats<<<592, 256>>>(buf1, dinv, conv_b + l * DCH, buf0, n, l);
    }
    // lin1 (K=256, BN fused on A-part) with fused lin2 epilogue -> d_out
    k_mma_gemm<<<gemm_grid, 256>>>(buf0, fair, l1h, l1l, l1b,
                                   gamma + 2 * DCH, beta + 2 * DCH, 2, nullptr, n, 2 * DCH, 1,
                                   l2w, l2b, (float*)d_out);
}

// round 16
// speedup vs baseline: 1.2084x; 1.0191x over previous
#include <cuda_runtime.h>
#include <cuda_bf16.h>
#include <cstdint>

#define DCH 128
#define NMAX 100000
#define EMAX 1600064

// ---------------- scratch (device globals; no runtime allocation) ----------------
__device__ float  g_buf0[NMAX * DCH];     // agg (pre-BN activations)
__device__ float  g_buf1[NMAX * DCH];     // gemm output t
__device__ __nv_bfloat16 g_wh[3 * DCH * DCH];   // conv W transposed [l][n][k] hi
__device__ __nv_bfloat16 g_wl[3 * DCH * DCH];
__device__ __nv_bfloat16 g_l1h[2 * DCH * DCH];  // lin1 W transposed [n][k=256] hi
__device__ __nv_bfloat16 g_l1l[2 * DCH * DCH];
__device__ int    g_degi[NMAX];
__device__ float  g_dinv[NMAX];
__device__ int    g_csr_off[NMAX + 1];
__device__ int    g_cursor[NMAX];
__device__ int    g_csr_src[EMAX];
__device__ int    g_bsum[256];
__device__ double g_sumA[3][DCH];     // per-layer BN stats (zeroed in k_wprep)
__device__ double g_sumqA[3][DCH];

// ---------------- helpers ----------------
__device__ __forceinline__ uint32_t sptr(const void* p) {
    return (uint32_t)__cvta_generic_to_shared(p);
}
__device__ __forceinline__ void ldsm4(unsigned r[4], uint32_t a) {
    asm volatile("ldmatrix.sync.aligned.m8n8.x4.shared.b16 {%0,%1,%2,%3}, [%4];\n"
                 : "=r"(r[0]), "=r"(r[1]), "=r"(r[2]), "=r"(r[3]) : "r"(a));
}
__device__ __forceinline__ void mma16816(float c[4], const unsigned a[4], const unsigned b[2]) {
    asm volatile(
        "mma.sync.aligned.m16n8k16.row.col.f32.bf16.bf16.f32 "
        "{%0,%1,%2,%3}, {%4,%5,%6,%7}, {%8,%9}, {%0,%1,%2,%3};\n"
        : "+f"(c[0]), "+f"(c[1]), "+f"(c[2]), "+f"(c[3])
        : "r"(a[0]), "r"(a[1]), "r"(a[2]), "r"(a[3]), "r"(b[0]), "r"(b[1]));
}
__device__ __forceinline__ void split_bf16(float v, __nv_bfloat16& h, __nv_bfloat16& l) {
    h = __float2bfloat16(v);
    l = __float2bfloat16(v - __bfloat162float(h));
}

// ---------------- degree ----------------
__global__ void k_deg_init(int* degi, int n) {
    int i = blockIdx.x * blockDim.x + threadIdx.x;
    if (i < n) degi[i] = 1;
}
__global__ void k_deg_count(const int* __restrict__ ei, int* degi, int E) {
    int e = blockIdx.x * blockDim.x + threadIdx.x;
    if (e < E) atomicAdd(&degi[ei[E + e]], 1);
}

// ---------------- CSR build (scan1 also computes dinv) ----------------
__global__ void k_scan1(const int* __restrict__ degi, float* __restrict__ dinv, int n) {
    __shared__ int sh[512];
    int i = blockIdx.x * 512 + threadIdx.x;
    int d = (i < n) ? degi[i] : 1;
    if (i < n) dinv[i] = rsqrtf((float)d);
    int v = (i < n) ? (d - 1) : 0;
    sh[threadIdx.x] = v;
    __syncthreads();
    int val = v;
#pragma unroll
    for (int off = 1; off < 512; off <<= 1) {
        int t = (threadIdx.x >= off) ? sh[threadIdx.x - off] : 0;
        __syncthreads();
        val += t;
        sh[threadIdx.x] = val;
        __syncthreads();
    }
    if (i < n) g_csr_off[i] = val - v;
    if (threadIdx.x == 511) g_bsum[blockIdx.x] = val;
}
__global__ void k_scan2(int nb, int n) {
    __shared__ int sh[256];
    int v = (threadIdx.x < nb) ? g_bsum[threadIdx.x] : 0;
    sh[threadIdx.x] = v;
    __syncthreads();
    int val = v;
#pragma unroll
    for (int off = 1; off < 256; off <<= 1) {
        int t = (threadIdx.x >= off) ? sh[threadIdx.x - off] : 0;
        __syncthreads();
        val += t;
        sh[threadIdx.x] = val;
        __syncthreads();
    }
    if (threadIdx.x < nb) g_bsum[threadIdx.x] = val - v;
    if (threadIdx.x == 255) g_csr_off[n] = val;
}
__global__ void k_scan3(int n) {
    int i = blockIdx.x * 512 + threadIdx.x;
    if (i < n) {
        int o = g_csr_off[i] + g_bsum[blockIdx.x];
        g_csr_off[i] = o;
        g_cursor[i]  = o;
    }
}
__global__ void k_fill(const int* __restrict__ ei, int E) {
    int e = blockIdx.x * blockDim.x + threadIdx.x;
    if (e < E) {
        int d = ei[E + e];
        int slot = atomicAdd(&g_cursor[d], 1);
        g_csr_src[slot] = ei[e];
    }
}

// ---------------- weight prep: transpose to [n][k], split; zero BN stats ----------
__global__ void k_wprep(const float* __restrict__ cw, const float* __restrict__ l1w) {
    int i = blockIdx.x * 256 + threadIdx.x;
    if (blockIdx.x == 0 && threadIdx.x < 128) {
#pragma unroll
        for (int l = 0; l < 3; l++) {
            g_sumA[l][threadIdx.x] = 0.0;
            g_sumqA[l][threadIdx.x] = 0.0;
        }
    }
    const int CONV = 3 * DCH * DCH;
    if (i < CONV) {
        int l = i / (DCH * DCH);
        int r = i % (DCH * DCH);
        int nn = r / DCH, k = r % DCH;
        float v = cw[(size_t)l * DCH * DCH + k * DCH + nn];
        split_bf16(v, g_wh[i], g_wl[i]);
    } else if (i < CONV + DCH * 2 * DCH) {
        int j = i - CONV;
        int nn = j / (2 * DCH), k = j % (2 * DCH);
        float v = l1w[(size_t)k * DCH + nn];
        split_bf16(v, g_l1h[j], g_l1l[j]);
    }
}

// ---------------- tensor-core GEMM (mma.sync) with fused BN(prev)+ReLU on A --------
// C[n,128] = f(A)[n,K] @ Wt[128,K]^T (+bias)(+relu_out)
// f(A) = relu(A*scale + shift) using stats buffer statIdx if statIdx >= 0.
// A2 (fp32, never BN'd) supplies k in [128,256) for lin1 concat.
// Split-bf16 3-term: C = Ah*Wh + Ah*Wl + Al*Wh.
// If W2 != null: fused second linear (lin2) writes OUT[n,40]; C unused.
__global__ __launch_bounds__(256, 2)
void k_mma_gemm(const float* __restrict__ A, const float* __restrict__ A2,
                const __nv_bfloat16* __restrict__ Bh, const __nv_bfloat16* __restrict__ Bl,
                const float* __restrict__ bias,
                const float* __restrict__ gamma, const float* __restrict__ beta,
                int statIdx,
                float* __restrict__ C, int n, int K, int relu,
                const float* __restrict__ W2, const float* __restrict__ b2,
                float* __restrict__ OUT)
{
    // flat smem: aliased regions
    //   [0,10240)      sAh   | after mainloop: W2s fp32 [0,20480)
    //   [10240,20480)  sAl   |
    //   [20480,30720)  sBh   | after mainloop: hstage fp32 32x132 [20480,37376)
    //   [30720,40960)  sBl   |
    //   [40960,41472)  sscale, [41472,41984) sshift
    __shared__ __align__(16) char SM[41984];
    __nv_bfloat16* sAh = (__nv_bfloat16*)(SM);
    __nv_bfloat16* sAl = (__nv_bfloat16*)(SM + 10240);
    __nv_bfloat16* sBh = (__nv_bfloat16*)(SM + 20480);
    __nv_bfloat16* sBl = (__nv_bfloat16*)(SM + 30720);
    float* sscale = (float*)(SM + 40960);
    float* sshift = (float*)(SM + 41472);

    const int tid = threadIdx.x, lane = tid & 31, wid = tid >> 5;
    const int wm = wid & 3;
    const int wn = wid >> 2;
    const int row0 = blockIdx.x * 128;
    const bool haveBN = (statIdx >= 0);

    if (tid < DCH) {
        if (haveBN) {
            double mu = g_sumA[statIdx][tid] / n;
            double var = g_sumqA[statIdx][tid] / n - mu * mu;
            float rs = (float)rsqrt(var + 1e-5);
            float g = gamma[tid] * rs;
            sscale[tid] = g;
            sshift[tid] = beta[tid] - (float)mu * g;
        } else {
            sscale[tid] = 1.f;
            sshift[tid] = 0.f;
        }
    }
    __syncthreads();

    float c[2][8][4];
#pragma unroll
    for (int i = 0; i < 2; i++)
#pragma unroll
        for (int j = 0; j < 8; j++)
#pragma unroll
            for (int q = 0; q < 4; q++) c[i][j][q] = 0.f;

    for (int kk = 0; kk < K; kk += 32) {
        const float* ap;
        int kb;
        bool isA;
        if (A2 != nullptr && kk >= 128) { ap = A2; kb = kk - 128; isA = false; }
        else                            { ap = A;  kb = kk; isA = true; }
        const bool bn = haveBN && isA;
        // A tile: fp32 load -> (BN+ReLU) -> split bf16 hi/lo -> smem
#pragma unroll
        for (int p = 0; p < 2; p++) {
            int idx = tid + p * 256;
            int r = idx >> 2, seg = idx & 3;
            int grow = row0 + r;
            float v[8];
#pragma unroll
            for (int q = 0; q < 8; q++) v[q] = 0.f;
            if (grow < n) {
                const float* base = ap + (size_t)grow * DCH + kb + seg * 8;
                *(float4*)&v[0] = *(const float4*)base;
                *(float4*)&v[4] = *(const float4*)(base + 4);
            }
            if (bn) {
                int c0 = kb + seg * 8;
#pragma unroll
                for (int q = 0; q < 8; q++)
                    v[q] = fmaxf(fmaf(v[q], sscale[c0 + q], sshift[c0 + q]), 0.f);
            }
            __nv_bfloat16 hb[8], lb[8];
#pragma unroll
            for (int q = 0; q < 8; q++) split_bf16(v[q], hb[q], lb[q]);
            *(uint4*)(sAh + r * 40 + seg * 8) = *(uint4*)hb;
            *(uint4*)(sAl + r * 40 + seg * 8) = *(uint4*)lb;
        }
        // B tile: pre-split bf16 weights
#pragma unroll
        for (int p = 0; p < 2; p++) {
            int idx = tid + p * 256;
            int r = idx >> 2, seg = idx & 3;
            size_t go = (size_t)r * K + kk + seg * 8;
            *(uint4*)(sBh + r * 40 + seg * 8) = *(const uint4*)(Bh + go);
            *(uint4*)(sBl + r * 40 + seg * 8) = *(const uint4*)(Bl + go);
        }
        __syncthreads();
#pragma unroll
        for (int kq = 0; kq < 2; kq++) {
            unsigned a_h[2][4], a_l[2][4], b_h[8][2], b_l[8][2];
            int arow = wm * 32 + (lane & 15);
            int akof = kq * 16 + ((lane & 16) ? 8 : 0);
#pragma unroll
            for (int i = 0; i < 2; i++) {
                ldsm4(a_h[i], sptr(sAh + (arow + i * 16) * 40 + akof));
                ldsm4(a_l[i], sptr(sAl + (arow + i * 16) * 40 + akof));
            }
            int bkof = kq * 16 + ((lane & 8) ? 8 : 0);
#pragma unroll
            for (int jp = 0; jp < 4; jp++) {
                int brow = wn * 64 + jp * 16 + ((lane & 16) ? 8 : 0) + (lane & 7);
                unsigned t[4];
                ldsm4(t, sptr(sBh + brow * 40 + bkof));
                b_h[jp * 2][0] = t[0]; b_h[jp * 2][1] = t[1];
                b_h[jp * 2 + 1][0] = t[2]; b_h[jp * 2 + 1][1] = t[3];
                ldsm4(t, sptr(sBl + brow * 40 + bkof));
                b_l[jp * 2][0] = t[0]; b_l[jp * 2][1] = t[1];
                b_l[jp * 2 + 1][0] = t[2]; b_l[jp * 2 + 1][1] = t[3];
            }
#pragma unroll
            for (int i = 0; i < 2; i++)
#pragma unroll
                for (int j = 0; j < 8; j++) {
                    mma16816(c[i][j], a_h[i], b_h[j]);
                    mma16816(c[i][j], a_h[i], b_l[j]);
                    mma16816(c[i][j], a_l[i], b_h[j]);
                }
        }
        __syncthreads();
    }

    if (W2 == nullptr) {
        // standard epilogue: bias + (relu) -> C
#pragma unroll
        for (int i = 0; i < 2; i++) {
#pragma unroll
            for (int j = 0; j < 8; j++) {
                int col = wn * 64 + j * 8 + (lane & 3) * 2;
                float b0 = bias ? bias[col] : 0.f;
                float b1 = bias ? bias[col + 1] : 0.f;
                int r0 = row0 + wm * 32 + i * 16 + (lane >> 2);
                float v0 = c[i][j][0] + b0, v1 = c[i][j][1] + b1;
                float v2 = c[i][j][2] + b0, v3 = c[i][j][3] + b1;
                if (relu) {
                    v0 = fmaxf(v0, 0.f); v1 = fmaxf(v1, 0.f);
                    v2 = fmaxf(v2, 0.f); v3 = fmaxf(v3, 0.f);
                }
                if (r0 < n)     *(float2*)(C + (size_t)r0 * DCH + col)       = make_float2(v0, v1);
                if (r0 + 8 < n) *(float2*)(C + (size_t)(r0 + 8) * DCH + col) = make_float2(v2, v3);
            }
        }
        return;
    }

    // ---- fused second linear: OUT[128 rows x 40] = relu(h) @ W2 + b2 ----
    float* W2s    = (float*)(SM);            // 128*40 fp32 = 20480 B
    float* hstage = (float*)(SM + 20480);    // 32 x 132 fp32 (padded) = 16896 B
    for (int i = tid; i < DCH * 40; i += 256) W2s[i] = W2[i];

    const int rl = tid >> 3;          // 0..31 local row
    const int q  = tid & 7;           // col group: q*5 .. q*5+4
    float bb[5];
#pragma unroll
    for (int j = 0; j < 5; j++) bb[j] = __ldg(&b2[q * 5 + j]);

    for (int cm = 0; cm < 4; cm++) {
        if (wm == cm) {
#pragma unroll
            for (int i = 0; i < 2; i++) {
#pragma unroll
                for (int j = 0; j < 8; j++) {
                    int col = wn * 64 + j * 8 + (lane & 3) * 2;
                    float b0 = bias[col], b1 = bias[col + 1];
                    int lr = i * 16 + (lane >> 2);
                    float v0 = fmaxf(c[i][j][0] + b0, 0.f);
                    float v1 = fmaxf(c[i][j][1] + b1, 0.f);
                    float v2 = fmaxf(c[i][j][2] + b0, 0.f);
                    float v3 = fmaxf(c[i][j][3] + b1, 0.f);
                    hstage[lr * 132 + col]       = v0;
                    hstage[lr * 132 + col + 1]   = v1;
                    hstage[(lr + 8) * 132 + col]     = v2;
                    hstage[(lr + 8) * 132 + col + 1] = v3;
                }
            }
        }
        __syncthreads();
        int grow = row0 + cm * 32 + rl;
        float acc[5];
#pragma unroll
        for (int j = 0; j < 5; j++) acc[j] = bb[j];
#pragma unroll 8
        for (int k = 0; k < DCH; k++) {
            float a = hstage[rl * 132 + k];
#pragma unroll
            for (int j = 0; j < 5; j++) acc[j] += a * W2s[k * 40 + q * 5 + j];
        }
        if (grow < n) {
#pragma unroll
            for (int j = 0; j < 5; j++) OUT[(size_t)grow * 40 + q * 5 + j] = acc[j];
        }
        __syncthreads();
    }
}

// ---------------- GCN aggregation + fused BN statistics ----------------
// occupancy pinned: 4 CTAs/SM, grid sized to one resident wave.
__global__ __launch_bounds__(256, 4)
void k_gather_stats(const float* __restrict__ t, const float* __restrict__ dinv,
                    const float* __restrict__ bias, float* __restrict__ agg,
                    int n, int statIdx)
{
    __shared__ float sS[DCH], sQ[DCH];
    if (threadIdx.x < DCH) {
        sS[threadIdx.x] = 0.f;
        sQ[threadIdx.x] = 0.f;
    }
    __syncthreads();

    int gw = (blockIdx.x * blockDim.x + threadIdx.x) >> 5;
    int lane = threadIdx.x & 31;
    int nw = (gridDim.x * blockDim.x) >> 5;
    float4 bv = __ldg((const float4*)bias + lane);
    float4 ps = make_float4(0.f, 0.f, 0.f, 0.f);
    float4 pq = make_float4(0.f, 0.f, 0.f, 0.f);

    for (int node = gw; node < n; node += nw) {
        float di = __ldg(&dinv[node]);
        float4 tv = __ldg((const float4*)(t + (size_t)node * DCH) + lane);
        float w0 = di * di;
        float4 acc;
        acc.x = bv.x + w0 * tv.x;
        acc.y = bv.y + w0 * tv.y;
        acc.z = bv.z + w0 * tv.z;
        acc.w = bv.w + w0 * tv.w;
        int beg = __ldg(&g_csr_off[node]);
        int end = __ldg(&g_csr_off[node + 1]);
        int j = beg;
#pragma unroll 1
        for (; j + 4 <= end; j += 4) {
            int s0 = __ldg(&g_csr_src[j]);
            int s1 = __ldg(&g_csr_src[j + 1]);
            int s2 = __ldg(&g_csr_src[j + 2]);
            int s3 = __ldg(&g_csr_src[j + 3]);
            float wa = di * __ldg(&dinv[s0]);
            float wb = di * __ldg(&dinv[s1]);
            float wc = di * __ldg(&dinv[s2]);
            float wd = di * __ldg(&dinv[s3]);
            float4 va = __ldg((const float4*)(t + (size_t)s0 * DCH) + lane);
            float4 vb = __ldg((const float4*)(t + (size_t)s1 * DCH) + lane);
            float4 vc = __ldg((const float4*)(t + (size_t)s2 * DCH) + lane);
            float4 vd = __ldg((const float4*)(t + (size_t)s3 * DCH) + lane);
            acc.x += wa * va.x; acc.y += wa * va.y; acc.z += wa * va.z; acc.w += wa * va.w;
            acc.x += wb * vb.x; acc.y += wb * vb.y; acc.z += wb * vb.z; acc.w += wb * vb.w;
            acc.x += wc * vc.x; acc.y += wc * vc.y; acc.z += wc * vc.z; acc.w += wc * vc.w;
            acc.x += wd * vd.x; acc.y += wd * vd.y; acc.z += wd * vd.z; acc.w += wd * vd.w;
        }
        for (; j < end; j++) {
            int s = __ldg(&g_csr_src[j]);
            float w = di * __ldg(&dinv[s]);
            float4 v = __ldg((const float4*)(t + (size_t)s * DCH) + lane);
            acc.x += w * v.x;
            acc.y += w * v.y;
            acc.z += w * v.z;
            acc.w += w * v.w;
        }
        *((float4*)(agg + (size_t)node * DCH) + lane) = acc;
        ps.x += acc.x; ps.y += acc.y; ps.z += acc.z; ps.w += acc.w;
        pq.x += acc.x * acc.x; pq.y += acc.y * acc.y;
        pq.z += acc.z * acc.z; pq.w += acc.w * acc.w;
    }

    int c0 = lane * 4;
    atomicAdd(&sS[c0 + 0], ps.x);
    atomicAdd(&sS[c0 + 1], ps.y);
    atomicAdd(&sS[c0 + 2], ps.z);
    atomicAdd(&sS[c0 + 3], ps.w);
    atomicAdd(&sQ[c0 + 0], pq.x);
    atomicAdd(&sQ[c0 + 1], pq.y);
    atomicAdd(&sQ[c0 + 2], pq.z);
    atomicAdd(&sQ[c0 + 3], pq.w);
    __syncthreads();
    if (threadIdx.x < DCH) {
        atomicAdd(&g_sumA[statIdx][threadIdx.x], (double)sS[threadIdx.x]);
        atomicAdd(&g_sumqA[statIdx][threadIdx.x], (double)sQ[threadIdx.x]);
    }
}

// ---------------- driver ----------------
extern "C" void kernel_launch(void* const* d_in, const int* in_sizes, int n_in,
                              void* d_out, int out_size)
{
    const float* x      = (const float*)d_in[0];
    const float* fair   = (const float*)d_in[1];
    const int*   ei     = (const int*)d_in[2];
    const float* conv_w = (const float*)d_in[3];
    const float* conv_b = (const float*)d_in[4];
    const float* gamma  = (const float*)d_in[5];
    const float* beta   = (const float*)d_in[6];
    const float* l1w    = (const float*)d_in[7];
    const float* l1b    = (const float*)d_in[8];
    const float* l2w    = (const float*)d_in[9];
    const float* l2b    = (const float*)d_in[10];

    int n = in_sizes[0] / DCH;
    int E = in_sizes[2] / 2;

    float *buf0, *buf1, *dinv;
    int *degi;
    __nv_bfloat16 *wh, *wl, *l1h, *l1l;
    cudaGetSymbolAddress((void**)&buf0, g_buf0);
    cudaGetSymbolAddress((void**)&buf1, g_buf1);
    cudaGetSymbolAddress((void**)&dinv, g_dinv);
    cudaGetSymbolAddress((void**)&degi, g_degi);
    cudaGetSymbolAddress((void**)&wh, g_wh);
    cudaGetSymbolAddress((void**)&wl, g_wl);
    cudaGetSymbolAddress((void**)&l1h, g_l1h);
    cudaGetSymbolAddress((void**)&l1l, g_l1l);

    // side stream + fork/join events for CSR-prep || gemm0 overlap
    // (created once; streams/events are not device-memory allocations)
    static cudaStream_t s2 = nullptr;
    static cudaEvent_t ev0 = nullptr, ev1 = nullptr;
    if (s2 == nullptr) {
        cudaStreamCreateWithFlags(&s2, cudaStreamNonBlocking);
        cudaEventCreateWithFlags(&ev0, cudaEventDisableTiming);
        cudaEventCreateWithFlags(&ev1, cudaEventDisableTiming);
    }

    int nb256 = (n + 255) / 256;
    int nbE   = (E + 255) / 256;
    int nb512 = (n + 511) / 512;
    int nbw   = (3 * DCH * DCH + DCH * 2 * DCH + 255) / 256;
    int gemm_grid = (n + 127) / 128;

    // fork: side stream builds CSR while main runs wprep + gemm0
    cudaEventRecord(ev0, 0);
    cudaStreamWaitEvent(s2, ev0, 0);

    k_wprep<<<nbw, 256>>>(conv_w, l1w);
    k_deg_init<<<nb256, 256, 0, s2>>>(degi, n);
    k_deg_count<<<nbE, 256, 0, s2>>>(ei, degi, E);
    k_mma_gemm<<<gemm_grid, 256>>>(x, nullptr, wh, wl, nullptr,
                                   nullptr, nullptr, -1, buf1, n, DCH, 0,
                                   nullptr, nullptr, nullptr);      // 4th launch: profiled
    k_scan1<<<nb512, 512, 0, s2>>>(degi, dinv, n);
    k_scan2<<<1, 256, 0, s2>>>(nb512, n);
    k_scan3<<<nb512, 512, 0, s2>>>(n);
    k_fill<<<nbE, 256, 0, s2>>>(ei, E);
    cudaEventRecord(ev1, s2);
    cudaStreamWaitEvent(0, ev1, 0);   // join before first gather

    for (int l = 0; l < 3; l++) {
        if (l > 0) {
            k_mma_gemm<<<gemm_grid, 256>>>(
                buf0, nullptr, wh + (size_t)l * DCH * DCH, wl + (size_t)l * DCH * DCH,
                nullptr, gamma + (l - 1) * DCH, beta + (l - 1) * DCH, l - 1,
                buf1, n, DCH, 0, nullptr, nullptr, nullptr);
        }
        k_gather_stats<<<592, 256>>>(buf1, dinv, conv_b + l * DCH, buf0, n, l);
    }
    // lin1 (K=256, BN fused on A-part) with fused lin2 epilogue -> d_out
    k_mma_gemm<<<gemm_grid, 256>>>(buf0, fair, l1h, l1l, l1b,
                                   gamma + 2 * DCH, beta + 2 * DCH, 2, nullptr, n, 2 * DCH, 1,
                                   l2w, l2b, (float*)d_out);
}